// round 13
// baseline (speedup 1.0000x reference)
#include <cuda_runtime.h>
#include <cuda_bf16.h>

// Problem constants (fixed-shape problem; grids still derived from in_sizes).
#define MAX_NODES 50000
#define CAP       128           // bucket capacity per node; P(deg>=128) ~ e^-150

// ---------------- device scratch (no allocations allowed) ----------------
__device__ int   g_deg[MAX_NODES];
__device__ int   g_bucket[MAX_NODES * CAP];     // 25.6 MB
__device__ float g_mean[MAX_NODES * 64];        // 12.8 MB
// Combined weight B[k][n] (k=in 0..127, n=out 0..127) pre-packed into
// mma.m16n8k16 B-fragment order: index [(kstep*16 + ntile)*32 + lane],
// uint2 = (b0, b1). Hi = bf16(v), Lo = bf16(v - hi).
__device__ __align__(16) uint2 g_WfH[8 * 16 * 32];   // 32 KB
__device__ __align__(16) uint2 g_WfL[8 * 16 * 32];   // 32 KB

// mma.sync m16n8k16 row.col f32.bf16.bf16.f32, D += A*B
#define MMA_BF16(d0, d1, d2, d3, a0, a1, a2, a3, b0, b1) \
    asm("mma.sync.aligned.m16n8k16.row.col.f32.bf16.bf16.f32 " \
        "{%0,%1,%2,%3}, {%4,%5,%6,%7}, {%8,%9}, {%0,%1,%2,%3};" \
        : "+f"(d0), "+f"(d1), "+f"(d2), "+f"(d3) \
        : "r"(a0), "r"(a1), "r"(a2), "r"(a3), "r"(b0), "r"(b1))

__device__ __forceinline__ float wval(const float* __restrict__ W_l,
                                      const float* __restrict__ W_r,
                                      int n, int k) {
    return (k < 64) ? W_l[n * 64 + k] : W_r[n * 64 + (k - 64)];
}

// split a float2 into packed bf16x2 hi and lo parts
__device__ __forceinline__ void split2(float2 v, unsigned int& h, unsigned int& l) {
    __nv_bfloat162 hp = __floats2bfloat162_rn(v.x, v.y);    // .x in low bits
    float h0 = __bfloat162float(hp.x);
    float h1 = __bfloat162float(hp.y);
    __nv_bfloat162 lp = __floats2bfloat162_rn(v.x - h0, v.y - h1);
    h = *(unsigned int*)&hp;
    l = *(unsigned int*)&lp;
}

// ---------------- kernel 1: zero degrees + build W fragment tables ----------
__global__ void k_init(const float* __restrict__ W_l,
                       const float* __restrict__ W_r, int nN) {
    int i = blockIdx.x * blockDim.x + threadIdx.x;
    if (i < nN) g_deg[i] = 0;
    if (i < 8 * 16 * 32) {
        int lane = i & 31;
        int nt   = (i >> 5) & 15;
        int ks   = i >> 9;
        int g    = lane >> 2;           // fragment "group" = n col within tile
        int t2   = (lane & 3) * 2;      // k row pair base
        int n    = nt * 8 + g;
        int k0   = ks * 16;
        // b0 = {B[k0+t2][n], B[k0+t2+1][n]}, b1 = rows +8
        float2 v0 = make_float2(wval(W_l, W_r, n, k0 + t2),
                                wval(W_l, W_r, n, k0 + t2 + 1));
        float2 v1 = make_float2(wval(W_l, W_r, n, k0 + t2 + 8),
                                wval(W_l, W_r, n, k0 + t2 + 9));
        unsigned int h0, l0, h1, l1;
        split2(v0, h0, l0);
        split2(v1, h1, l1);
        g_WfH[i] = make_uint2(h0, h1);
        g_WfL[i] = make_uint2(l0, l1);
    }
}

// ---------------- kernel 2: bucket fill (CSR-lite, no scan) ----------------
__global__ void k_fill_buckets(const int* __restrict__ ei, int nE, int nN) {
    int e = blockIdx.x * blockDim.x + threadIdx.x;
    if (e >= nE) return;
    int s = ei[e];               // src row   (edge_index[0][e])
    int d = ei[nE + e];          // dst row   (edge_index[1][e])
    if ((unsigned)s >= (unsigned)nN || (unsigned)d >= (unsigned)nN) return;
    int slot = atomicAdd(&g_deg[d], 1);
    if (slot < CAP) g_bucket[d * CAP + slot] = s;
}

// ---------------- kernel 3: mean aggregation (best measured version) ----------
__global__ void k_aggregate(const float* __restrict__ x, int nN) {
    int gwarp = (blockIdx.x * blockDim.x + threadIdx.x) >> 5;
    int lane  = threadIdx.x & 31;
    if (gwarp >= nN) return;
    int node = gwarp;
    int deg  = g_deg[node];
    int m    = min(deg, CAP);

    const float4* __restrict__ x4 = (const float4*)x;
    const int* __restrict__ bkt = &g_bucket[node * CAP];

    int col  = lane & 15;
    int half = lane >> 4;

    float4 acc = make_float4(0.f, 0.f, 0.f, 0.f);
    for (int base = 0; base < m; base += 32) {
        int cnt = min(32, m - base);
        int sid = (lane < cnt) ? bkt[base + lane] : -1;
        int pairs = (cnt + 1) >> 1;
        #pragma unroll 4
        for (int p = 0; p < pairs; p++) {
            int s = __shfl_sync(0xffffffffu, sid, 2 * p + half);
            if (s >= 0) {
                float4 v = x4[(size_t)s * 16 + col];
                acc.x += v.x; acc.y += v.y;
                acc.z += v.z; acc.w += v.w;
            }
        }
    }
    acc.x += __shfl_xor_sync(0xffffffffu, acc.x, 16);
    acc.y += __shfl_xor_sync(0xffffffffu, acc.y, 16);
    acc.z += __shfl_xor_sync(0xffffffffu, acc.z, 16);
    acc.w += __shfl_xor_sync(0xffffffffu, acc.w, 16);

    if (half == 0) {
        float inv = 1.0f / fmaxf((float)deg, 1.0f);
        acc.x *= inv; acc.y *= inv; acc.z *= inv; acc.w *= inv;
        ((float4*)g_mean)[(size_t)node * 16 + col] = acc;
    }
}

// ---------------- kernel 4: tensor-core GEMM via mma.sync (bf16 3-term split) --
// out[m, n] = sum_k A[m,k] * B[k,n] + bias[n],  A = [mean || x] (K=128)
// D = Ah*Bh + Ah*Bl + Al*Bh in fp32 accumulators (dropped Al*Bl <= 2^-18 rel).
// CTA: 64 nodes x 128 outs, 8 warps = 4 m-groups x 2 n-halves.
// Warp: 16 rows x 8 n-tiles x 8 k-steps, 3 HMMA each = 192 HMMA/warp.
// acc = 32 fp32 regs/thread -> ~80 regs -> 3 CTAs/SM (24 warps).
__global__ void __launch_bounds__(256, 3)
k_gemm_mma(const float* __restrict__ x,
           const float* __restrict__ b_l,
           float* __restrict__ out, int nN) {
    int tid   = threadIdx.x;
    int wid   = tid >> 5;
    int lane  = tid & 31;
    int g     = lane >> 2;          // row within tile (and +8)
    int t2    = (lane & 3) * 2;     // col pair base (A cols / D cols)
    int mgrp  = wid & 3;            // m-group 0..3 (16 rows each)
    int nhalf = wid >> 2;           // n-half 0..1 (8 n-tiles each)
    int nt0   = nhalf * 8;

    int row0 = blockIdx.x * 64 + mgrp * 16 + g;
    int row1 = row0 + 8;
    int nM   = nN - 1;
    size_t ro0 = (size_t)min(row0, nM) * 32;   // float2 row offsets (64 floats)
    size_t ro1 = (size_t)min(row1, nM) * 32;

    const float2* __restrict__ mean2 = (const float2*)g_mean;
    const float2* __restrict__ x2    = (const float2*)x;

    // accumulators: acc[nt][0..3]; c0,c1 = row g cols t2,t2+1; c2,c3 = row g+8
    float acc[8][4];
    #pragma unroll
    for (int nt = 0; nt < 8; nt++) {
        float b0 = b_l[(nt0 + nt) * 8 + t2];
        float b1 = b_l[(nt0 + nt) * 8 + t2 + 1];
        acc[nt][0] = b0; acc[nt][1] = b1;
        acc[nt][2] = b0; acc[nt][3] = b1;
    }

    #pragma unroll 1
    for (int ks = 0; ks < 8; ks++) {
        int k0 = ks * 16;
        const float2* __restrict__ src = (k0 < 64) ? mean2 : x2;
        int cb2 = ((k0 & 63) + t2) >> 1;       // float2 col index
        // A fragment: a0=(g, t2), a1=(g+8, t2), a2=(g, t2+8), a3=(g+8, t2+8)
        float2 v0 = src[ro0 + cb2];
        float2 v1 = src[ro1 + cb2];
        float2 v2 = src[ro0 + cb2 + 4];
        float2 v3 = src[ro1 + cb2 + 4];
        unsigned int ah0, ah1, ah2, ah3, al0, al1, al2, al3;
        split2(v0, ah0, al0);
        split2(v1, ah1, al1);
        split2(v2, ah2, al2);
        split2(v3, ah3, al3);

        const uint2* __restrict__ wh = &g_WfH[(ks * 16 + nt0) * 32 + lane];
        const uint2* __restrict__ wl = &g_WfL[(ks * 16 + nt0) * 32 + lane];
        #pragma unroll
        for (int nt = 0; nt < 8; nt++) {
            uint2 bh = wh[nt * 32];
            uint2 bl = wl[nt * 32];
            MMA_BF16(acc[nt][0], acc[nt][1], acc[nt][2], acc[nt][3],
                     ah0, ah1, ah2, ah3, bh.x, bh.y);
            MMA_BF16(acc[nt][0], acc[nt][1], acc[nt][2], acc[nt][3],
                     ah0, ah1, ah2, ah3, bl.x, bl.y);
            MMA_BF16(acc[nt][0], acc[nt][1], acc[nt][2], acc[nt][3],
                     al0, al1, al2, al3, bh.x, bh.y);
        }
    }

    // stores: float2 per (row, ntile); quad lanes cover 32B contiguous
    bool ok0 = row0 < nN;
    bool ok1 = row1 < nN;
    float* o0 = &out[(size_t)row0 * 128 + nt0 * 8 + t2];
    float* o1 = &out[(size_t)row1 * 128 + nt0 * 8 + t2];
    #pragma unroll
    for (int nt = 0; nt < 8; nt++) {
        if (ok0) *(float2*)(o0 + nt * 8) = make_float2(acc[nt][0], acc[nt][1]);
        if (ok1) *(float2*)(o1 + nt * 8) = make_float2(acc[nt][2], acc[nt][3]);
    }
}

// ---------------- launch ----------------
extern "C" void kernel_launch(void* const* d_in, const int* in_sizes, int n_in,
                              void* d_out, int out_size) {
    const float* x   = (const float*)d_in[0];       // [N, 64]
    const int*   ei  = (const int*)d_in[1];         // [2, E] int32 (JAX x64 off)
    const float* W_l = (const float*)d_in[2];       // [128, 64]
    const float* b_l = (const float*)d_in[3];       // [128]
    const float* W_r = (const float*)d_in[4];       // [128, 64]
    float*       out = (float*)d_out;               // [N, 128]

    int nN = in_sizes[0] / 64;
    int nE = in_sizes[1] / 2;

    int initN = (nN > 8 * 16 * 32) ? nN : 8 * 16 * 32;
    k_init<<<(initN + 255) / 256, 256>>>(W_l, W_r, nN);
    k_fill_buckets<<<(nE + 255) / 256, 256>>>(ei, nE, nN);
    k_aggregate<<<(nN + 7) / 8, 256>>>(x, nN);
    k_gemm_mma<<<(nN + 63) / 64, 256>>>(x, b_l, out, nN);
}

// round 14
// speedup vs baseline: 1.0024x; 1.0024x over previous
#include <cuda_runtime.h>
#include <cuda_bf16.h>

// Problem constants (fixed-shape problem; grids still derived from in_sizes).
#define MAX_NODES 50000
#define CAP       128           // bucket capacity per node; P(deg>=128) ~ e^-150

// ---------------- device scratch (no allocations allowed) ----------------
__device__ int   g_deg[MAX_NODES];
__device__ int   g_bucket[MAX_NODES * CAP];     // 25.6 MB
__device__ float g_mean[MAX_NODES * 64];        // 12.8 MB
// Combined weight B[k][n] (k=in 0..127, n=out 0..127) pre-packed into
// mma.m16n8k16 B-fragment order: index [(kstep*16 + ntile)*32 + lane],
// uint2 = (b0, b1). Hi = bf16(v), Lo = bf16(v - hi).
__device__ __align__(16) uint2 g_WfH[8 * 16 * 32];   // 32 KB
__device__ __align__(16) uint2 g_WfL[8 * 16 * 32];   // 32 KB

// mma.sync m16n8k16 row.col f32.bf16.bf16.f32, D += A*B
#define MMA_BF16(d0, d1, d2, d3, a0, a1, a2, a3, b0, b1) \
    asm("mma.sync.aligned.m16n8k16.row.col.f32.bf16.bf16.f32 " \
        "{%0,%1,%2,%3}, {%4,%5,%6,%7}, {%8,%9}, {%0,%1,%2,%3};" \
        : "+f"(d0), "+f"(d1), "+f"(d2), "+f"(d3) \
        : "r"(a0), "r"(a1), "r"(a2), "r"(a3), "r"(b0), "r"(b1))

__device__ __forceinline__ float wval(const float* __restrict__ W_l,
                                      const float* __restrict__ W_r,
                                      int n, int k) {
    return (k < 64) ? W_l[n * 64 + k] : W_r[n * 64 + (k - 64)];
}

// split a float2 into packed bf16x2 hi and lo parts
__device__ __forceinline__ void split2(float2 v, unsigned int& h, unsigned int& l) {
    __nv_bfloat162 hp = __floats2bfloat162_rn(v.x, v.y);    // .x in low bits
    float h0 = __bfloat162float(hp.x);
    float h1 = __bfloat162float(hp.y);
    __nv_bfloat162 lp = __floats2bfloat162_rn(v.x - h0, v.y - h1);
    h = *(unsigned int*)&hp;
    l = *(unsigned int*)&lp;
}

// ---------------- kernel 1: zero degrees + build W fragment tables ----------
__global__ void k_init(const float* __restrict__ W_l,
                       const float* __restrict__ W_r, int nN) {
    int i = blockIdx.x * blockDim.x + threadIdx.x;
    if (i < nN) g_deg[i] = 0;
    if (i < 8 * 16 * 32) {
        int lane = i & 31;
        int nt   = (i >> 5) & 15;
        int ks   = i >> 9;
        int g    = lane >> 2;           // fragment "group" = n col within tile
        int t2   = (lane & 3) * 2;      // k row pair base
        int n    = nt * 8 + g;
        int k0   = ks * 16;
        // b0 = {B[k0+t2][n], B[k0+t2+1][n]}, b1 = rows +8
        float2 v0 = make_float2(wval(W_l, W_r, n, k0 + t2),
                                wval(W_l, W_r, n, k0 + t2 + 1));
        float2 v1 = make_float2(wval(W_l, W_r, n, k0 + t2 + 8),
                                wval(W_l, W_r, n, k0 + t2 + 9));
        unsigned int h0, l0, h1, l1;
        split2(v0, h0, l0);
        split2(v1, h1, l1);
        g_WfH[i] = make_uint2(h0, h1);
        g_WfL[i] = make_uint2(l0, l1);
    }
}

// ---------------- kernel 2: bucket fill (CSR-lite, no scan) ----------------
__global__ void k_fill_buckets(const int* __restrict__ ei, int nE, int nN) {
    int e = blockIdx.x * blockDim.x + threadIdx.x;
    if (e >= nE) return;
    int s = ei[e];               // src row   (edge_index[0][e])
    int d = ei[nE + e];          // dst row   (edge_index[1][e])
    if ((unsigned)s >= (unsigned)nN || (unsigned)d >= (unsigned)nN) return;
    int slot = atomicAdd(&g_deg[d], 1);
    if (slot < CAP) g_bucket[d * CAP + slot] = s;
}

// ---------------- kernel 3: mean aggregation (best measured version) ----------
__global__ void k_aggregate(const float* __restrict__ x, int nN) {
    int gwarp = (blockIdx.x * blockDim.x + threadIdx.x) >> 5;
    int lane  = threadIdx.x & 31;
    if (gwarp >= nN) return;
    int node = gwarp;
    int deg  = g_deg[node];
    int m    = min(deg, CAP);

    const float4* __restrict__ x4 = (const float4*)x;
    const int* __restrict__ bkt = &g_bucket[node * CAP];

    int col  = lane & 15;
    int half = lane >> 4;

    float4 acc = make_float4(0.f, 0.f, 0.f, 0.f);
    for (int base = 0; base < m; base += 32) {
        int cnt = min(32, m - base);
        int sid = (lane < cnt) ? bkt[base + lane] : -1;
        int pairs = (cnt + 1) >> 1;
        #pragma unroll 4
        for (int p = 0; p < pairs; p++) {
            int s = __shfl_sync(0xffffffffu, sid, 2 * p + half);
            if (s >= 0) {
                float4 v = x4[(size_t)s * 16 + col];
                acc.x += v.x; acc.y += v.y;
                acc.z += v.z; acc.w += v.w;
            }
        }
    }
    acc.x += __shfl_xor_sync(0xffffffffu, acc.x, 16);
    acc.y += __shfl_xor_sync(0xffffffffu, acc.y, 16);
    acc.z += __shfl_xor_sync(0xffffffffu, acc.z, 16);
    acc.w += __shfl_xor_sync(0xffffffffu, acc.w, 16);

    if (half == 0) {
        float inv = 1.0f / fmaxf((float)deg, 1.0f);
        acc.x *= inv; acc.y *= inv; acc.z *= inv; acc.w *= inv;
        ((float4*)g_mean)[(size_t)node * 16 + col] = acc;
    }
}

// ---------------- kernel 4: tensor-core GEMM via mma.sync (bf16 3-term split) --
// out[m, n] = sum_k A[m,k] * B[k,n] + bias[n],  A = [mean || x] (K=128)
// D = Ah*Bh + Ah*Bl + Al*Bh in fp32 accumulators (dropped Al*Bl <= 2^-18 rel).
// CTA: 128 nodes, 8 warps; warp w owns rows [blockM + w*16, +16), all 16 n-tiles.
// A loads are COLD (each row read once) -> 2-deep software pipeline across the
// 8 k-steps hides the ~400-600cyc DRAM/L2 latency behind two HMMA blocks.
__global__ void __launch_bounds__(256, 2)
k_gemm_mma(const float* __restrict__ x,
           const float* __restrict__ b_l,
           float* __restrict__ out, int nN) {
    int tid  = threadIdx.x;
    int wid  = tid >> 5;
    int lane = tid & 31;
    int g    = lane >> 2;           // row within tile (and +8)
    int t2   = (lane & 3) * 2;      // col pair base (A cols / D cols)

    int row0 = blockIdx.x * 128 + wid * 16 + g;
    int row1 = row0 + 8;
    int nM   = nN - 1;
    size_t ro0 = (size_t)min(row0, nM) * 32;   // float2 row offsets (64 floats)
    size_t ro1 = (size_t)min(row1, nM) * 32;

    const float2* __restrict__ mean2 = (const float2*)g_mean;
    const float2* __restrict__ x2    = (const float2*)x;

    // A-fragment loader for k-step ks (clamped; redundant loads are harmless)
    auto loadA = [&](int ks, float2& v0, float2& v1, float2& v2, float2& v3) {
        ks = min(ks, 7);
        const float2* __restrict__ src = (ks < 4) ? mean2 : x2;
        int cb2 = (((ks * 16) & 63) + t2) >> 1;
        v0 = __ldg(&src[ro0 + cb2]);
        v1 = __ldg(&src[ro1 + cb2]);
        v2 = __ldg(&src[ro0 + cb2 + 4]);
        v3 = __ldg(&src[ro1 + cb2 + 4]);
    };

    // prime the pipeline: A(0) and A(1) in flight before anything else
    float2 c0, c1, c2, c3, n0v, n1v, n2v, n3v;
    loadA(0, c0, c1, c2, c3);
    loadA(1, n0v, n1v, n2v, n3v);

    // accumulators: acc[nt][0..3]; [0],[1] = row g cols t2,t2+1; [2],[3] = row g+8
    float acc[16][4];
    #pragma unroll
    for (int nt = 0; nt < 16; nt++) {
        float b0 = b_l[nt * 8 + t2];
        float b1 = b_l[nt * 8 + t2 + 1];
        acc[nt][0] = b0; acc[nt][1] = b1;
        acc[nt][2] = b0; acc[nt][3] = b1;
    }

    #pragma unroll 1
    for (int ks = 0; ks < 8; ks++) {
        // issue loads for ks+2 immediately (independent of this iter's compute)
        float2 f0, f1, f2, f3;
        loadA(ks + 2, f0, f1, f2, f3);

        unsigned int ah0, ah1, ah2, ah3, al0, al1, al2, al3;
        split2(c0, ah0, al0);
        split2(c1, ah1, al1);
        split2(c2, ah2, al2);
        split2(c3, ah3, al3);

        const uint2* __restrict__ wh = &g_WfH[(ks * 16) * 32 + lane];
        const uint2* __restrict__ wl = &g_WfL[(ks * 16) * 32 + lane];
        #pragma unroll
        for (int nt = 0; nt < 16; nt++) {
            uint2 bh = wh[nt * 32];
            uint2 bl = wl[nt * 32];
            MMA_BF16(acc[nt][0], acc[nt][1], acc[nt][2], acc[nt][3],
                     ah0, ah1, ah2, ah3, bh.x, bh.y);
            MMA_BF16(acc[nt][0], acc[nt][1], acc[nt][2], acc[nt][3],
                     ah0, ah1, ah2, ah3, bl.x, bl.y);
            MMA_BF16(acc[nt][0], acc[nt][1], acc[nt][2], acc[nt][3],
                     al0, al1, al2, al3, bh.x, bh.y);
        }

        // rotate pipeline buffers
        c0 = n0v; c1 = n1v; c2 = n2v; c3 = n3v;
        n0v = f0; n1v = f1; n2v = f2; n3v = f3;
    }

    // stores: float2 per (row, ntile); quad lanes cover 32B contiguous
    bool ok0 = row0 < nN;
    bool ok1 = row1 < nN;
    float* o0 = &out[(size_t)row0 * 128 + t2];
    float* o1 = &out[(size_t)row1 * 128 + t2];
    #pragma unroll
    for (int nt = 0; nt < 16; nt++) {
        if (ok0) *(float2*)(o0 + nt * 8) = make_float2(acc[nt][0], acc[nt][1]);
        if (ok1) *(float2*)(o1 + nt * 8) = make_float2(acc[nt][2], acc[nt][3]);
    }
}

// ---------------- launch ----------------
extern "C" void kernel_launch(void* const* d_in, const int* in_sizes, int n_in,
                              void* d_out, int out_size) {
    const float* x   = (const float*)d_in[0];       // [N, 64]
    const int*   ei  = (const int*)d_in[1];         // [2, E] int32 (JAX x64 off)
    const float* W_l = (const float*)d_in[2];       // [128, 64]
    const float* b_l = (const float*)d_in[3];       // [128]
    const float* W_r = (const float*)d_in[4];       // [128, 64]
    float*       out = (float*)d_out;               // [N, 128]

    int nN = in_sizes[0] / 64;
    int nE = in_sizes[1] / 2;

    int initN = (nN > 8 * 16 * 32) ? nN : 8 * 16 * 32;
    k_init<<<(initN + 255) / 256, 256>>>(W_l, W_r, nN);
    k_fill_buckets<<<(nE + 255) / 256, 256>>>(ei, nE, nN);
    k_aggregate<<<(nN + 7) / 8, 256>>>(x, nN);
    k_gemm_mma<<<(nN + 127) / 128, 256>>>(x, b_l, out, nN);
}

// round 15
// speedup vs baseline: 1.0978x; 1.0952x over previous
#include <cuda_runtime.h>
#include <cuda_bf16.h>

// Problem constants (fixed-shape problem; grids still derived from in_sizes).
#define MAX_NODES 50000
#define CAP       128           // bucket capacity per node; P(deg>=128) ~ e^-150

// ---------------- device scratch (no allocations allowed) ----------------
__device__ int   g_deg[MAX_NODES];
__device__ int   g_bucket[MAX_NODES * CAP];     // 25.6 MB
__device__ float g_mean[MAX_NODES * 64];        // 12.8 MB
// Combined weight B[k][n] (k=in 0..127, n=out 0..127) pre-packed into
// mma.m16n8k16 B-fragment order: index [(kstep*16 + ntile)*32 + lane],
// uint2 = (b0, b1). Hi = bf16(v), Lo = bf16(v - hi).
__device__ __align__(16) uint2 g_WfH[8 * 16 * 32];   // 32 KB
__device__ __align__(16) uint2 g_WfL[8 * 16 * 32];   // 32 KB

// mma.sync m16n8k16 row.col f32.bf16.bf16.f32, D += A*B
#define MMA_BF16(d0, d1, d2, d3, a0, a1, a2, a3, b0, b1) \
    asm("mma.sync.aligned.m16n8k16.row.col.f32.bf16.bf16.f32 " \
        "{%0,%1,%2,%3}, {%4,%5,%6,%7}, {%8,%9}, {%0,%1,%2,%3};" \
        : "+f"(d0), "+f"(d1), "+f"(d2), "+f"(d3) \
        : "r"(a0), "r"(a1), "r"(a2), "r"(a3), "r"(b0), "r"(b1))

__device__ __forceinline__ float wval(const float* __restrict__ W_l,
                                      const float* __restrict__ W_r,
                                      int n, int k) {
    return (k < 64) ? W_l[n * 64 + k] : W_r[n * 64 + (k - 64)];
}

// split a float2 into packed bf16x2 hi and lo parts
__device__ __forceinline__ void split2(float2 v, unsigned int& h, unsigned int& l) {
    __nv_bfloat162 hp = __floats2bfloat162_rn(v.x, v.y);    // .x in low bits
    float h0 = __bfloat162float(hp.x);
    float h1 = __bfloat162float(hp.y);
    __nv_bfloat162 lp = __floats2bfloat162_rn(v.x - h0, v.y - h1);
    h = *(unsigned int*)&hp;
    l = *(unsigned int*)&lp;
}

// ---------------- kernel 1: zero degrees + build W fragment tables ----------
__global__ void k_init(const float* __restrict__ W_l,
                       const float* __restrict__ W_r, int nN) {
    int i = blockIdx.x * blockDim.x + threadIdx.x;
    if (i < nN) g_deg[i] = 0;
    if (i < 8 * 16 * 32) {
        int lane = i & 31;
        int nt   = (i >> 5) & 15;
        int ks   = i >> 9;
        int g    = lane >> 2;           // fragment "group" = n col within tile
        int t2   = (lane & 3) * 2;      // k row pair base
        int n    = nt * 8 + g;
        int k0   = ks * 16;
        // b0 = {B[k0+t2][n], B[k0+t2+1][n]}, b1 = rows +8
        float2 v0 = make_float2(wval(W_l, W_r, n, k0 + t2),
                                wval(W_l, W_r, n, k0 + t2 + 1));
        float2 v1 = make_float2(wval(W_l, W_r, n, k0 + t2 + 8),
                                wval(W_l, W_r, n, k0 + t2 + 9));
        unsigned int h0, l0, h1, l1;
        split2(v0, h0, l0);
        split2(v1, h1, l1);
        g_WfH[i] = make_uint2(h0, h1);
        g_WfL[i] = make_uint2(l0, l1);
    }
}

// ---------------- kernel 2: bucket fill (CSR-lite, no scan) ----------------
__global__ void k_fill_buckets(const int* __restrict__ ei, int nE, int nN) {
    int e = blockIdx.x * blockDim.x + threadIdx.x;
    if (e >= nE) return;
    int s = ei[e];               // src row   (edge_index[0][e])
    int d = ei[nE + e];          // dst row   (edge_index[1][e])
    if ((unsigned)s >= (unsigned)nN || (unsigned)d >= (unsigned)nN) return;
    int slot = atomicAdd(&g_deg[d], 1);
    if (slot < CAP) g_bucket[d * CAP + slot] = s;
}

// ---------------- kernel 3: mean aggregation (best measured version) ----------
__global__ void k_aggregate(const float* __restrict__ x, int nN) {
    int gwarp = (blockIdx.x * blockDim.x + threadIdx.x) >> 5;
    int lane  = threadIdx.x & 31;
    if (gwarp >= nN) return;
    int node = gwarp;
    int deg  = g_deg[node];
    int m    = min(deg, CAP);

    const float4* __restrict__ x4 = (const float4*)x;
    const int* __restrict__ bkt = &g_bucket[node * CAP];

    int col  = lane & 15;
    int half = lane >> 4;

    float4 acc = make_float4(0.f, 0.f, 0.f, 0.f);
    for (int base = 0; base < m; base += 32) {
        int cnt = min(32, m - base);
        int sid = (lane < cnt) ? bkt[base + lane] : -1;
        int pairs = (cnt + 1) >> 1;
        #pragma unroll 4
        for (int p = 0; p < pairs; p++) {
            int s = __shfl_sync(0xffffffffu, sid, 2 * p + half);
            if (s >= 0) {
                float4 v = x4[(size_t)s * 16 + col];
                acc.x += v.x; acc.y += v.y;
                acc.z += v.z; acc.w += v.w;
            }
        }
    }
    acc.x += __shfl_xor_sync(0xffffffffu, acc.x, 16);
    acc.y += __shfl_xor_sync(0xffffffffu, acc.y, 16);
    acc.z += __shfl_xor_sync(0xffffffffu, acc.z, 16);
    acc.w += __shfl_xor_sync(0xffffffffu, acc.w, 16);

    if (half == 0) {
        float inv = 1.0f / fmaxf((float)deg, 1.0f);
        acc.x *= inv; acc.y *= inv; acc.z *= inv; acc.w *= inv;
        ((float4*)g_mean)[(size_t)node * 16 + col] = acc;
    }
}

// ---------------- kernel 4: tensor-core GEMM via mma.sync (bf16 3-term split) --
// out[m, n] = sum_k A[m,k] * B[k,n] + bias[n],  A = [mean || x] (K=128)
// D = Ah*Bh + Ah*Bl + Al*Bh in fp32 accumulators (dropped Al*Bl <= 2^-18 rel).
// CTA: 128 nodes, 8 warps; warp w owns rows [blockM + w*16, +16), all 16 n-tiles.
// Inner loop runs THREE PASSES over the 16 n-tiles (one per split term) so all
// 16 MMAs in a pass hit distinct accumulators -> no RAW chain, full pipelining.
__global__ void __launch_bounds__(256, 2)
k_gemm_mma(const float* __restrict__ x,
           const float* __restrict__ b_l,
           float* __restrict__ out, int nN) {
    int tid  = threadIdx.x;
    int wid  = tid >> 5;
    int lane = tid & 31;
    int g    = lane >> 2;           // row within tile (and +8)
    int t2   = (lane & 3) * 2;      // col pair base (A cols / D cols)

    int row0 = blockIdx.x * 128 + wid * 16 + g;
    int row1 = row0 + 8;
    int nM   = nN - 1;
    size_t ro0 = (size_t)min(row0, nM) * 32;   // float2 row offsets (64 floats)
    size_t ro1 = (size_t)min(row1, nM) * 32;

    const float2* __restrict__ mean2 = (const float2*)g_mean;
    const float2* __restrict__ x2    = (const float2*)x;

    // accumulators: acc[nt][0..3]; [0],[1] = row g cols t2,t2+1; [2],[3] = row g+8
    float acc[16][4];
    #pragma unroll
    for (int nt = 0; nt < 16; nt++) {
        float b0 = b_l[nt * 8 + t2];
        float b1 = b_l[nt * 8 + t2 + 1];
        acc[nt][0] = b0; acc[nt][1] = b1;
        acc[nt][2] = b0; acc[nt][3] = b1;
    }

    #pragma unroll 1
    for (int ks = 0; ks < 8; ks++) {
        int k0 = ks * 16;
        const float2* __restrict__ src = (k0 < 64) ? mean2 : x2;
        int cb2 = ((k0 & 63) + t2) >> 1;       // float2 col index
        // A fragment: a0=(g, t2), a1=(g+8, t2), a2=(g, t2+8), a3=(g+8, t2+8)
        float2 v0 = src[ro0 + cb2];
        float2 v1 = src[ro1 + cb2];
        float2 v2 = src[ro0 + cb2 + 4];
        float2 v3 = src[ro1 + cb2 + 4];
        unsigned int ah0, ah1, ah2, ah3, al0, al1, al2, al3;
        split2(v0, ah0, al0);
        split2(v1, ah1, al1);
        split2(v2, ah2, al2);
        split2(v3, ah3, al3);

        const uint2* __restrict__ wh = &g_WfH[(ks * 16) * 32 + lane];
        const uint2* __restrict__ wl = &g_WfL[(ks * 16) * 32 + lane];

        // pass 1: Ah * Bh  (16 independent MMAs)
        #pragma unroll
        for (int nt = 0; nt < 16; nt++) {
            uint2 bh = wh[nt * 32];
            MMA_BF16(acc[nt][0], acc[nt][1], acc[nt][2], acc[nt][3],
                     ah0, ah1, ah2, ah3, bh.x, bh.y);
        }
        // pass 2: Ah * Bl  (16 independent MMAs; acc reuse is 16-MMA distant)
        #pragma unroll
        for (int nt = 0; nt < 16; nt++) {
            uint2 bl = wl[nt * 32];
            MMA_BF16(acc[nt][0], acc[nt][1], acc[nt][2], acc[nt][3],
                     ah0, ah1, ah2, ah3, bl.x, bl.y);
        }
        // pass 3: Al * Bh  (re-reads wh from L1)
        #pragma unroll
        for (int nt = 0; nt < 16; nt++) {
            uint2 bh = wh[nt * 32];
            MMA_BF16(acc[nt][0], acc[nt][1], acc[nt][2], acc[nt][3],
                     al0, al1, al2, al3, bh.x, bh.y);
        }
    }

    // stores: float2 per (row, ntile); quad lanes cover 32B contiguous
    bool ok0 = row0 < nN;
    bool ok1 = row1 < nN;
    float* o0 = &out[(size_t)row0 * 128 + t2];
    float* o1 = &out[(size_t)row1 * 128 + t2];
    #pragma unroll
    for (int nt = 0; nt < 16; nt++) {
        if (ok0) *(float2*)(o0 + nt * 8) = make_float2(acc[nt][0], acc[nt][1]);
        if (ok1) *(float2*)(o1 + nt * 8) = make_float2(acc[nt][2], acc[nt][3]);
    }
}

// ---------------- launch ----------------
extern "C" void kernel_launch(void* const* d_in, const int* in_sizes, int n_in,
                              void* d_out, int out_size) {
    const float* x   = (const float*)d_in[0];       // [N, 64]
    const int*   ei  = (const int*)d_in[1];         // [2, E] int32 (JAX x64 off)
    const float* W_l = (const float*)d_in[2];       // [128, 64]
    const float* b_l = (const float*)d_in[3];       // [128]
    const float* W_r = (const float*)d_in[4];       // [128, 64]
    float*       out = (float*)d_out;               // [N, 128]

    int nN = in_sizes[0] / 64;
    int nE = in_sizes[1] / 2;

    int initN = (nN > 8 * 16 * 32) ? nN : 8 * 16 * 32;
    k_init<<<(initN + 255) / 256, 256>>>(W_l, W_r, nN);
    k_fill_buckets<<<(nE + 255) / 256, 256>>>(ei, nE, nN);
    k_aggregate<<<(nN + 7) / 8, 256>>>(x, nN);
    k_gemm_mma<<<(nN + 127) / 128, 256>>>(x, b_l, out, nN);
}